// round 5
// baseline (speedup 1.0000x reference)
#include <cuda_runtime.h>

typedef unsigned long long ull;

#define BATCH 32
#define NATOM 128
#define HH 64
#define WW 64
#define OH 57
#define SPP (OH*OH)           // 3249
#define NPS (NATOM*SPP)       // 415872
#define KSEL 256
#define NAL 17
#define CAP 1024
#define NBINS 4096
#define IMGPIX (HH*WW)        // 4096
#define LBUF 1536
#define POOLCAP (32*LBUF)
#define HSZ 1024

// ---------------- device state ----------------
__device__ float d_R[BATCH*IMGPIX];
__device__ int   d_hist[BATCH*NBINS];
__device__ int   d_shash[BATCH*HSZ];
__device__ int   d_pcnt[BATCH];
__device__ int   d_pool_pos[BATCH*POOLCAP];
__device__ float d_pool_g[BATCH*POOLCAP];
__device__ float d_gsupp[BATCH*KSEL];
__device__ int   d_ccnt[BATCH];
__device__ int   d_cpos[BATCH*CAP];
__device__ float d_cg[BATCH*CAP];
__device__ float d_cx[BATCH*CAP];
__device__ int   d_selp[NAL*BATCH*KSEL];
__device__ float d_selv[NAL*BATCH*KSEL];
__device__ float d_errp[NAL*BATCH];
__device__ float d_l2p[BATCH];
__device__ int   d_supp[BATCH*KSEL];
__device__ int   d_nsup[BATCH];

__device__ __forceinline__ int binof(float g) {
    return (int)((__float_as_uint(g) & 0x7fffffffu) >> 19);
}

// inclusive suffix sum over blockDim.x per-thread values
__device__ __forceinline__ int suffix_scan(int v, volatile int* wtmp, int nwarp) {
    int lane = threadIdx.x & 31, wid = threadIdx.x >> 5;
    int x = v;
    #pragma unroll
    for (int off = 1; off < 32; off <<= 1) {
        int u = __shfl_down_sync(0xffffffffu, x, off);
        if (lane + off < 32) x += u;
    }
    if (lane == 0) wtmp[wid] = x;
    __syncthreads();
    int add = 0;
    for (int j = wid + 1; j < nwarp; j++) add += wtmp[j];
    return x + add;
}

// ---------------- kernels ----------------

__global__ void k_init(float* __restrict__ X) {
    int stride = gridDim.x * blockDim.x;
    for (int i = blockIdx.x * blockDim.x + threadIdx.x; i < BATCH*NPS; i += stride)
        X[i] = 0.f;
    if (blockIdx.x == 0 && threadIdx.x < BATCH) d_nsup[threadIdx.x] = 0;
}

// residual R = Y - conv_D(X_sparse); l2; g at support; supp hash; zero hist/counters
__global__ void k_residual(const float* __restrict__ Y, const float* __restrict__ Wg,
                           const float* __restrict__ X) {
    __shared__ float syh[IMGPIX];
    __shared__ float sred[8];
    int s = blockIdx.x, tid = threadIdx.x;
    if (tid == 0) { d_ccnt[s] = 0; d_pcnt[s] = 0; }
    for (int i = tid; i < HSZ; i += 256) d_shash[s*HSZ + i] = 0;
    for (int i = tid; i < NBINS; i += 256) d_hist[s*NBINS + i] = 0;
    for (int i = tid; i < IMGPIX; i += 256) syh[i] = 0.f;
    __syncthreads();
    int ns = d_nsup[s];
    int pos = -1;
    if (tid < ns) pos = d_supp[s*KSEL + tid];
    if (pos >= 0) {
        float val = X[s*NPS + pos];
        int a = pos / SPP, rem = pos - a*SPP, u = rem / OH, v = rem - u*OH;
        const float* w = Wg + a*64;
        #pragma unroll
        for (int p = 0; p < 8; p++)
            #pragma unroll
            for (int q = 0; q < 8; q++)
                atomicAdd(&syh[(u+p)*WW + v + q], val * w[p*8 + q]);
        unsigned h = ((unsigned)pos * 2654435761u >> 22) & (HSZ - 1);
        while (atomicCAS(&d_shash[s*HSZ + h], 0, pos + 1) != 0) h = (h + 1) & (HSZ - 1);
    }
    __syncthreads();
    float e = 0.f;
    for (int i = tid; i < IMGPIX; i += 256) {
        float r = Y[s*IMGPIX + i] - syh[i];
        d_R[s*IMGPIX + i] = r;
        syh[i] = r;
        e += r*r;
    }
    __syncthreads();
    // g at support positions (same accumulation order as k_conv_cand)
    if (tid < ns) {
        float g = 0.f;
        if (pos >= 0) {
            int a = pos / SPP, rem = pos - a*SPP, u = rem / OH, v = rem - u*OH;
            const float* w = Wg + a*64;
            #pragma unroll
            for (int p = 0; p < 8; p++)
                #pragma unroll
                for (int q = 0; q < 8; q++)
                    g = fmaf(syh[(u+p)*WW + v + q], w[q*8 + p], g);
        }
        d_gsupp[s*KSEL + tid] = g;
    }
    for (int o = 16; o; o >>= 1) e += __shfl_down_sync(0xffffffffu, e, o);
    if ((tid & 31) == 0) sred[tid >> 5] = e;
    __syncthreads();
    if (tid < 32) {
        e = (tid < 8) ? sred[tid] : 0.f;
        for (int o = 4; o; o >>= 1) e += __shfl_down_sync(0xffffffffu, e, o);
        if (tid == 0) d_l2p[s] = e;
    }
}

// conv (FFMA2) + exact global hist + local top-512-superset push (no probing)
// grid: 32 samples x 8 atom-groups x 4 u-chunks = 1024 blocks, 256 threads.
__global__ void __launch_bounds__(256) k_conv_cand(const float* __restrict__ Wg) {
    __shared__ float shR[23*64 + 16];
    __shared__ float shW[64*16];      // [p*8+q][a]
    __shared__ int   shH[NBINS];
    __shared__ int   sbp[LBUF];
    __shared__ float sbg[LBUF];
    __shared__ int   wtmp[8];
    __shared__ int   s_lthr, s_bcnt, s_base;

    int bid = blockIdx.x;
    int s   = bid >> 5;
    int rem = bid & 31;
    int grp = rem >> 2;
    int uc  = rem & 3;
    int ub  = uc * 16;
    int abase = grp * 16;
    int tid = threadIdx.x;

    for (int i = tid; i < NBINS; i += 256) shH[i] = 0;
    for (int i = tid; i < 23*64; i += 256) {
        int r = ub + (i >> 6);
        shR[i] = (r < HH) ? d_R[s*IMGPIX + r*WW + (i & 63)] : 0.f;
    }
    if (tid < 16) shR[23*64 + tid] = 0.f;
    for (int i = tid; i < 1024; i += 256) {
        int a = i & 15, pq = i >> 4, p = pq >> 3, q = pq & 7;
        shW[pq*16 + a] = Wg[(abase + a)*64 + q*8 + p];
    }
    if (tid == 0) s_bcnt = 0;
    __syncthreads();

    int v  = tid & 63;
    int ty = tid >> 6;
    int u0 = ty * 4;

    ull acc[8][4];
    #pragma unroll
    for (int ap = 0; ap < 8; ap++)
        #pragma unroll
        for (int uu = 0; uu < 4; uu++) acc[ap][uu] = 0ull;

    #pragma unroll 1
    for (int p = 0; p < 8; p++) {
        #pragma unroll
        for (int q = 0; q < 8; q++) {
            ull w2[8];
            const ull* wrow = (const ull*)&shW[(p*8 + q)*16];
            #pragma unroll
            for (int ap = 0; ap < 8; ap++) w2[ap] = wrow[ap];
            #pragma unroll
            for (int uu = 0; uu < 4; uu++) {
                float r = shR[(u0 + uu + p)*64 + v + q];
                ull r2;
                asm("mov.b64 %0, {%1, %1};" : "=l"(r2) : "f"(r));
                #pragma unroll
                for (int ap = 0; ap < 8; ap++)
                    asm("fma.rn.f32x2 %0, %1, %2, %0;"
                        : "+l"(acc[ap][uu]) : "l"(w2[ap]), "l"(r2));
            }
        }
    }

    bool vok = (v < OH);
    #pragma unroll
    for (int uu = 0; uu < 4; uu++) {
        int u = ub + u0 + uu;
        if (vok && u < OH) {
            #pragma unroll
            for (int ap = 0; ap < 8; ap++) {
                float lo, hi;
                asm("mov.b64 {%0, %1}, %2;" : "=f"(lo), "=f"(hi) : "l"(acc[ap][uu]));
                atomicAdd(&shH[binof(lo)], 1);
                atomicAdd(&shH[binof(hi)], 1);
            }
        }
    }
    __syncthreads();

    // local threshold: smallest bin with suffix-count >= 512 (covers global top-256
    // off-support even if up to 256 support values outrank locally)
    int seg = 0;
    #pragma unroll
    for (int j = 0; j < 16; j++) seg += shH[tid*16 + j];
    int ss = suffix_scan(seg, wtmp, 8);
    int low = ss - seg;
    if (ss >= 512 && low < 512) {
        int cum = low;
        for (int j = 15; j >= 0; j--) {
            cum += shH[tid*16 + j];
            if (cum >= 512) { s_lthr = tid*16 + j; break; }
        }
    }
    for (int i = tid; i < NBINS; i += 256)
        if (shH[i]) atomicAdd(&d_hist[s*NBINS + i], shH[i]);
    __syncthreads();
    int lthr = s_lthr;

    #pragma unroll
    for (int uu = 0; uu < 4; uu++) {
        int u = ub + u0 + uu;
        if (vok && u < OH) {
            #pragma unroll
            for (int ap = 0; ap < 8; ap++) {
                float gv2[2];
                asm("mov.b64 {%0, %1}, %2;" : "=f"(gv2[0]), "=f"(gv2[1]) : "l"(acc[ap][uu]));
                #pragma unroll
                for (int half = 0; half < 2; half++) {
                    float gv = gv2[half];
                    if (binof(gv) >= lthr) {
                        int idx = atomicAdd(&s_bcnt, 1);
                        if (idx < LBUF) {
                            sbp[idx] = (abase + 2*ap + half)*SPP + u*OH + v;
                            sbg[idx] = gv;
                        }
                    }
                }
            }
        }
    }
    __syncthreads();
    int cnt = s_bcnt; if (cnt > LBUF) cnt = LBUF;
    if (tid == 0) s_base = atomicAdd(&d_pcnt[s], cnt);
    __syncthreads();
    int base = s_base;
    for (int i = tid; i < cnt; i += 256) {
        int gi = base + i;
        d_pool_pos[s*POOLCAP + gi] = sbp[i];
        d_pool_g[s*POOLCAP + gi]   = sbg[i];
    }
}

// grid (9, 32): chunks 0..7 compact non-support pool entries above global thr;
// chunk 8 appends support entries (with X values).
__global__ void __launch_bounds__(512) k_compact(const float* __restrict__ X) {
    __shared__ int wtmp[16];
    __shared__ int s_thr;
    int chunk = blockIdx.x, s = blockIdx.y, tid = threadIdx.x;

    if (chunk == 8) {
        int ns = d_nsup[s];
        if (tid < ns) {
            int pos = d_supp[s*KSEL + tid];
            if (pos >= 0) {
                int slot = atomicAdd(&d_ccnt[s], 1);
                if (slot < CAP) {
                    d_cpos[s*CAP + slot] = pos;
                    d_cg[s*CAP + slot]   = d_gsupp[s*KSEL + tid];
                    d_cx[s*CAP + slot]   = X[s*NPS + pos];
                }
            }
        }
        return;
    }
    const int* hist = &d_hist[s*NBINS];
    int seg = 0;
    #pragma unroll
    for (int j = 0; j < 8; j++) seg += hist[tid*8 + j];
    int ss = suffix_scan(seg, wtmp, 16);
    int low = ss - seg;
    if (ss >= 2*KSEL && low < 2*KSEL) {
        int cum = low;
        for (int j = 7; j >= 0; j--) {
            cum += hist[tid*8 + j];
            if (cum >= 2*KSEL) { s_thr = tid*8 + j; break; }
        }
    }
    __syncthreads();
    int thr = s_thr;
    int n_pool = d_pcnt[s];
    const int* shash = &d_shash[s*HSZ];
    for (int i = chunk*512 + tid; i < n_pool; i += 8*512) {
        float g = d_pool_g[s*POOLCAP + i];
        if (binof(g) >= thr) {
            int pos = d_pool_pos[s*POOLCAP + i];
            unsigned h = ((unsigned)pos * 2654435761u >> 22) & (HSZ - 1);
            bool insup = false;
            while (true) {
                int hv = shash[h];
                if (hv == 0) break;
                if (hv == pos + 1) { insup = true; break; }
                h = (h + 1) & (HSZ - 1);
            }
            if (!insup) {
                int slot = atomicAdd(&d_ccnt[s], 1);
                if (slot < CAP) {
                    d_cpos[s*CAP + slot] = pos;
                    d_cg[s*CAP + slot]   = g;
                    d_cx[s*CAP + slot]   = 0.f;
                }
            }
        }
    }
}

// one block per (alpha, sample): exact top-256 via O(n^2) rank-count, recon + err
__global__ void __launch_bounds__(512) k_attempt(const float* __restrict__ Y,
                                                 const float* __restrict__ Wg) {
    __shared__ ull   skey[CAP];
    __shared__ float sval[CAP];
    __shared__ float syh[IMGPIX];
    __shared__ float sred[16];
    __shared__ int   s_cnt;

    int ka = blockIdx.x, s = blockIdx.y, tid = threadIdx.x;
    float alpha = 1.0f / (float)(1 << ka);
    int n = d_ccnt[s]; if (n > CAP) n = CAP;

    #pragma unroll
    for (int ii = 0; ii < 2; ii++) {
        int i = tid + ii*512;
        ull kk = 0ull; float val = 0.f;
        if (i < n) {
            int pos = d_cpos[s*CAP + i];
            val = d_cx[s*CAP + i] + alpha * d_cg[s*CAP + i];
            unsigned ab = __float_as_uint(val) & 0x7fffffffu;
            kk = ((ull)ab << 19) | (unsigned)((~pos) & 0x7ffff);
        }
        skey[i] = kk; sval[i] = val;
    }
    for (int i = tid; i < IMGPIX; i += 512) syh[i] = 0.f;
    if (tid == 0) s_cnt = 0;
    __syncthreads();

    // rank = count of strictly greater keys (keys unique)
    ull k0 = skey[tid], k1 = skey[tid + 512];
    int c0 = 0, c1 = 0;
    #pragma unroll 4
    for (int j = 0; j < n; j++) {
        ull k = skey[j];
        c0 += (k > k0);
        c1 += (k > k1);
    }

    int selbase = (ka*BATCH + s)*KSEL;
    #pragma unroll
    for (int ii = 0; ii < 2; ii++) {
        int i = tid + ii*512;
        int c = ii ? c1 : c0;
        if (i < n && c < KSEL) {
            int slot = atomicAdd(&s_cnt, 1);
            ull k = ii ? k1 : k0;
            int pos = (int)((~(unsigned)k) & 0x7ffff);
            float val = sval[i];
            d_selp[selbase + slot] = pos;
            d_selv[selbase + slot] = val;
            int a = pos / SPP, rem2 = pos - a*SPP, u = rem2 / OH, vv = rem2 - u*OH;
            const float* w = Wg + a*64;
            #pragma unroll
            for (int p = 0; p < 8; p++)
                #pragma unroll
                for (int q = 0; q < 8; q++)
                    atomicAdd(&syh[(u+p)*WW + vv + q], val * w[p*8 + q]);
        }
    }
    __syncthreads();
    float e = 0.f;
    for (int i = tid; i < IMGPIX; i += 512) {
        float d = Y[s*IMGPIX + i] - syh[i];
        e += d*d;
    }
    for (int o = 16; o; o >>= 1) e += __shfl_down_sync(0xffffffffu, e, o);
    if ((tid & 31) == 0) sred[tid >> 5] = e;
    __syncthreads();
    if (tid < 32) {
        e = (tid < 16) ? sred[tid] : 0.f;
        for (int o = 8; o; o >>= 1) e += __shfl_down_sync(0xffffffffu, e, o);
        if (tid == 0) d_errp[ka*BATCH + s] = e;
    }
}

// commit: redundant per-block alpha choice, scatter-update X + support
__global__ void k_commit(float* __restrict__ X) {
    __shared__ int sc;
    int s = blockIdx.x, tid = threadIdx.x;
    if (tid == 0) {
        float l2 = 0.f;
        for (int s2 = 0; s2 < BATCH; s2++) l2 += d_l2p[s2];
        int c = NAL - 1;
        for (int k = 0; k < NAL; k++) {
            float e = 0.f;
            for (int s2 = 0; s2 < BATCH; s2++) e += d_errp[k*BATCH + s2];
            if (e < l2) { c = k; break; }
        }
        sc = c;
    }
    int ns = d_nsup[s];
    if (tid < ns) {
        int p = d_supp[s*KSEL + tid];
        if (p >= 0) X[s*NPS + p] = 0.f;
    }
    __syncthreads();
    int c = sc;
    int pos = d_selp[(c*BATCH + s)*KSEL + tid];
    float val = d_selv[(c*BATCH + s)*KSEL + tid];
    if (pos >= 0) X[s*NPS + pos] = val;
    d_supp[s*KSEL + tid] = pos;
    if (tid == 0) d_nsup[s] = KSEL;
}

// ---------------- launch ----------------
extern "C" void kernel_launch(void* const* d_in, const int* in_sizes, int n_in,
                              void* d_out, int out_size) {
    const float* Y  = (const float*)d_in[0];
    const float* Wg = (const float*)d_in[1];
    float* X = (float*)d_out;

    k_init<<<2048, 256>>>(X);
    for (int it = 0; it < 3; it++) {
        k_residual<<<BATCH, 256>>>(Y, Wg, X);
        k_conv_cand<<<1024, 256>>>(Wg);
        k_compact<<<dim3(9, BATCH), 512>>>(X);
        k_attempt<<<dim3(NAL, BATCH), 512>>>(Y, Wg);
        k_commit<<<BATCH, KSEL>>>(X);
    }
}

// round 6
// speedup vs baseline: 1.3124x; 1.3124x over previous
#include <cuda_runtime.h>

typedef unsigned long long ull;

#define BATCH 32
#define NATOM 128
#define HH 64
#define WW 64
#define OH 57
#define SPP (OH*OH)           // 3249
#define NPS (NATOM*SPP)       // 415872
#define KSEL 256
#define NAL 17
#define CAP 2048
#define NBINS 4096
#define IMGPIX (HH*WW)        // 4096

// ---------------- device state ----------------
__device__ float d_R[BATCH*IMGPIX];
__device__ float d_g[BATCH*NPS];              // ~53 MB
__device__ int   d_hist[BATCH*NBINS];
__device__ int   d_ccnt[BATCH];
__device__ int   d_cpos[BATCH*CAP];
__device__ float d_cg[BATCH*CAP];
__device__ float d_cx[BATCH*CAP];
__device__ int   d_selp[NAL*BATCH*KSEL];
__device__ float d_selv[NAL*BATCH*KSEL];
__device__ float d_errp[NAL*BATCH];
__device__ float d_l2p[BATCH];
__device__ int   d_supp[BATCH*KSEL];
__device__ int   d_nsup[BATCH];

__device__ __forceinline__ int binof(float g) {
    return (int)((__float_as_uint(g) & 0x7fffffffu) >> 19);
}

// inclusive suffix sum over blockDim.x per-thread values
__device__ __forceinline__ int suffix_scan(int v, volatile int* wtmp, int nwarp) {
    int lane = threadIdx.x & 31, wid = threadIdx.x >> 5;
    int x = v;
    #pragma unroll
    for (int off = 1; off < 32; off <<= 1) {
        int u = __shfl_down_sync(0xffffffffu, x, off);
        if (lane + off < 32) x += u;
    }
    if (lane == 0) wtmp[wid] = x;
    __syncthreads();
    int add = 0;
    for (int j = wid + 1; j < nwarp; j++) add += wtmp[j];
    return x + add;
}

// ---------------- kernels ----------------

__global__ void k_init(float* __restrict__ X) {
    int stride = gridDim.x * blockDim.x;
    for (int i = blockIdx.x * blockDim.x + threadIdx.x; i < BATCH*NPS; i += stride)
        X[i] = 0.f;
    if (blockIdx.x == 0 && threadIdx.x < BATCH) d_nsup[threadIdx.x] = 0;
}

__global__ void k_iter_init() {
    int gid = blockIdx.x * blockDim.x + threadIdx.x;   // 512*256 = BATCH*NBINS
    d_hist[gid] = 0;
    if (gid < BATCH) d_ccnt[gid] = 0;
}

// residual R = Y - conv_D(X_sparse); per-sample l2
__global__ void k_residual(const float* __restrict__ Y, const float* __restrict__ Wg,
                           const float* __restrict__ X) {
    __shared__ float syh[IMGPIX];
    __shared__ float sred[8];
    int s = blockIdx.x, tid = threadIdx.x;
    for (int i = tid; i < IMGPIX; i += 256) syh[i] = 0.f;
    __syncthreads();
    int ns = d_nsup[s];
    if (tid < ns) {
        int pos = d_supp[s*KSEL + tid];
        if (pos >= 0) {
            float val = X[s*NPS + pos];
            int a = pos / SPP, rem = pos - a*SPP, u = rem / OH, v = rem - u*OH;
            const float* w = Wg + a*64;
            #pragma unroll
            for (int p = 0; p < 8; p++)
                #pragma unroll
                for (int q = 0; q < 8; q++)
                    atomicAdd(&syh[(u+p)*WW + v + q], val * w[p*8 + q]);
        }
    }
    __syncthreads();
    float e = 0.f;
    for (int i = tid; i < IMGPIX; i += 256) {
        float r = Y[s*IMGPIX + i] - syh[i];
        d_R[s*IMGPIX + i] = r;
        e += r*r;
    }
    for (int o = 16; o; o >>= 1) e += __shfl_down_sync(0xffffffffu, e, o);
    if ((tid & 31) == 0) sred[tid >> 5] = e;
    __syncthreads();
    if (tid < 32) {
        e = (tid < 8) ? sred[tid] : 0.f;
        for (int o = 4; o; o >>= 1) e += __shfl_down_sync(0xffffffffu, e, o);
        if (tid == 0) d_l2p[s] = e;
    }
}

// g[b,a,u,v] = sum_{p,q} R[b,u+p,v+q] * W[a,q,p]; fused |g| histogram.
// grid: 32 samples x 8 atom-groups x 4 u-chunks = 1024 blocks, 256 threads.
__global__ void __launch_bounds__(256) k_conv_g(const float* __restrict__ Wg) {
    __shared__ float shR[23*64 + 16];
    __shared__ float shW[64*16];      // [p*8+q][a]
    __shared__ int   shH[NBINS];
    int bid = blockIdx.x;
    int s   = bid >> 5;
    int rem = bid & 31;
    int grp = rem >> 2;
    int uc  = rem & 3;
    int ub  = uc * 16;
    int abase = grp * 16;
    int tid = threadIdx.x;

    for (int i = tid; i < NBINS; i += 256) shH[i] = 0;
    for (int i = tid; i < 23*64; i += 256) {
        int r = ub + (i >> 6);
        shR[i] = (r < HH) ? d_R[s*IMGPIX + r*WW + (i & 63)] : 0.f;
    }
    if (tid < 16) shR[23*64 + tid] = 0.f;
    for (int i = tid; i < 1024; i += 256) {
        int a = i & 15, pq = i >> 4, p = pq >> 3, q = pq & 7;
        shW[pq*16 + a] = Wg[(abase + a)*64 + q*8 + p];
    }
    __syncthreads();

    int v  = tid & 63;
    int ty = tid >> 6;
    int u0 = ty * 4;

    ull acc[8][4];
    #pragma unroll
    for (int ap = 0; ap < 8; ap++)
        #pragma unroll
        for (int uu = 0; uu < 4; uu++) acc[ap][uu] = 0ull;

    #pragma unroll 1
    for (int p = 0; p < 8; p++) {
        #pragma unroll
        for (int q = 0; q < 8; q++) {
            ull w2[8];
            const ull* wrow = (const ull*)&shW[(p*8 + q)*16];
            #pragma unroll
            for (int ap = 0; ap < 8; ap++) w2[ap] = wrow[ap];
            #pragma unroll
            for (int uu = 0; uu < 4; uu++) {
                float r = shR[(u0 + uu + p)*64 + v + q];
                ull r2;
                asm("mov.b64 %0, {%1, %1};" : "=l"(r2) : "f"(r));
                #pragma unroll
                for (int ap = 0; ap < 8; ap++)
                    asm("fma.rn.f32x2 %0, %1, %2, %0;"
                        : "+l"(acc[ap][uu]) : "l"(w2[ap]), "l"(r2));
            }
        }
    }

    bool vok = (v < OH);
    #pragma unroll
    for (int uu = 0; uu < 4; uu++) {
        int u = ub + u0 + uu;
        if (vok && u < OH) {
            int base = s*NPS + abase*SPP + u*OH + v;
            #pragma unroll
            for (int ap = 0; ap < 8; ap++) {
                float lo, hi;
                asm("mov.b64 {%0, %1}, %2;" : "=f"(lo), "=f"(hi) : "l"(acc[ap][uu]));
                d_g[base + (2*ap)*SPP]   = lo;
                d_g[base + (2*ap+1)*SPP] = hi;
                atomicAdd(&shH[binof(lo)], 1);
                atomicAdd(&shH[binof(hi)], 1);
            }
        }
    }
    __syncthreads();
    for (int i = tid; i < NBINS; i += 256)
        if (shH[i]) atomicAdd(&d_hist[s*NBINS + i], shH[i]);
}

// grid (52, 32): per-block redundant threshold (suffix scan over exact hist),
// chunks 0..50 scan dense g; chunk 51 appends support entries below threshold.
// cx read from dense X: 0.0 off-support automatically, X value on support.
__global__ void __launch_bounds__(256) k_collect(const float* __restrict__ X) {
    __shared__ int wtmp[8];
    __shared__ int s_thr;
    int s = blockIdx.y, chunk = blockIdx.x, tid = threadIdx.x;

    // redundant per-block threshold from exact global hist (top-512 bin)
    const int* hist = &d_hist[s*NBINS];
    int seg = 0;
    #pragma unroll
    for (int j = 0; j < 16; j++) seg += hist[tid*16 + j];
    int ss = suffix_scan(seg, wtmp, 8);
    int low = ss - seg;
    if (ss >= 2*KSEL && low < 2*KSEL) {
        int cum = low;
        for (int j = 15; j >= 0; j--) {
            cum += hist[tid*16 + j];
            if (cum >= 2*KSEL) { s_thr = tid*16 + j; break; }
        }
    }
    __syncthreads();
    int thr = s_thr;

    if (chunk == 51) {
        int ns = d_nsup[s];
        if (tid < ns) {
            int pos = d_supp[s*KSEL + tid];
            if (pos >= 0) {
                float gv = d_g[s*NPS + pos];
                if (binof(gv) < thr) {
                    int idx = atomicAdd(&d_ccnt[s], 1);
                    if (idx < CAP) {
                        d_cpos[s*CAP + idx] = pos;
                        d_cg[s*CAP + idx]   = gv;
                        d_cx[s*CAP + idx]   = X[s*NPS + pos];
                    }
                }
            }
        }
        return;
    }
    int base = chunk * 8192;
    int end = base + 8192; if (end > NPS) end = NPS;
    for (int i = base + tid; i < end; i += 256) {
        float gv = d_g[s*NPS + i];
        if (binof(gv) >= thr) {
            int idx = atomicAdd(&d_ccnt[s], 1);
            if (idx < CAP) {
                d_cpos[s*CAP + idx] = i;
                d_cg[s*CAP + idx]   = gv;
                d_cx[s*CAP + idx]   = X[s*NPS + i];
            }
        }
    }
}

// one block per (alpha, sample): exact top-256 via 12-bit radix-select on unique
// 51-bit keys (abs<<19 | ~pos); then sparse reconstruction + err.
__global__ void __launch_bounds__(512) k_attempt(const float* __restrict__ Y,
                                                 const float* __restrict__ Wg) {
    __shared__ ull   skey[CAP];
    __shared__ float sval[CAP];
    __shared__ unsigned aux[NBINS];   // digit hist, later syh
    __shared__ int   wtmp[16];
    __shared__ ull   s_prefix, s_T;
    __shared__ int   s_m, s_done, s_cnt;
    __shared__ float sred[16];

    int ka = blockIdx.x, s = blockIdx.y, tid = threadIdx.x;
    float alpha = 1.0f / (float)(1 << ka);
    int n = d_ccnt[s]; if (n > CAP) n = CAP;

    for (int i = tid; i < CAP; i += 512) {
        ull kk = 0ull; float val = 0.f;
        if (i < n) {
            int pos = d_cpos[s*CAP + i];
            val = d_cx[s*CAP + i] + alpha * d_cg[s*CAP + i];
            unsigned ab = __float_as_uint(val) & 0x7fffffffu;
            kk = ((ull)ab << 19) | (unsigned)((~pos) & 0x7ffff);
        }
        skey[i] = kk; sval[i] = val;
    }
    if (tid == 0) { s_prefix = 0ull; s_m = KSEL; s_done = (n <= KSEL) ? 1 : 0; s_T = 1ull; }

    for (int lvl = 0; lvl < 5; lvl++) {
        __syncthreads();
        int done = s_done; ull pref = s_prefix; int m = s_m;
        int shift = 48 - 12*lvl;
        if (!done) {
            for (int i = tid; i < NBINS; i += 512) aux[i] = 0u;
            __syncthreads();
            ull himask = ~(((ull)1 << (shift + 12)) - 1);
            for (int i = tid; i < n; i += 512) {
                ull k = skey[i];
                if ((k & himask) == pref)
                    atomicAdd(&aux[(unsigned)((k >> shift) & 0xFFF)], 1u);
            }
            __syncthreads();
            int seg = 0;
            #pragma unroll
            for (int j = 0; j < 8; j++) seg += (int)aux[tid*8 + j];
            int ss = suffix_scan(seg, wtmp, 16);
            int low = ss - seg;
            if (ss >= m && low < m) {
                int cum = low, b = tid*8, h_b = 0;
                for (int j = 7; j >= 0; j--) {
                    int c = (int)aux[tid*8 + j];
                    cum += c;
                    if (cum >= m) { b = tid*8 + j; h_b = c; break; }
                }
                ull npref = pref | ((ull)b << shift);
                if (cum == m || shift == 0) { s_T = npref; s_done = 1; }
                else { s_prefix = npref; s_m = m - (cum - h_b); }
            }
        } else {
            __syncthreads();
        }
    }
    __syncthreads();
    ull T = s_T;

    int selbase = (ka*BATCH + s)*KSEL;
    if (tid < KSEL) d_selp[selbase + tid] = -1;
    for (int i = tid; i < IMGPIX; i += 512) aux[i] = 0u;
    if (tid == 0) s_cnt = 0;
    __syncthreads();

    float* syh = (float*)aux;
    for (int i = tid; i < n; i += 512) {
        ull k = skey[i];
        if (k >= T) {
            int slot = atomicAdd(&s_cnt, 1);
            int pos = (int)((~(unsigned)k) & 0x7ffff);
            float val = sval[i];
            d_selp[selbase + slot] = pos;
            d_selv[selbase + slot] = val;
            int a = pos / SPP, rem2 = pos - a*SPP, u = rem2 / OH, vv = rem2 - u*OH;
            const float* w = Wg + a*64;
            #pragma unroll
            for (int p = 0; p < 8; p++)
                #pragma unroll
                for (int q = 0; q < 8; q++)
                    atomicAdd(&syh[(u+p)*WW + vv + q], val * w[p*8 + q]);
        }
    }
    __syncthreads();
    float e = 0.f;
    for (int i = tid; i < IMGPIX; i += 512) {
        float d = Y[s*IMGPIX + i] - syh[i];
        e += d*d;
    }
    for (int o = 16; o; o >>= 1) e += __shfl_down_sync(0xffffffffu, e, o);
    if ((tid & 31) == 0) sred[tid >> 5] = e;
    __syncthreads();
    if (tid < 32) {
        e = (tid < 16) ? sred[tid] : 0.f;
        for (int o = 8; o; o >>= 1) e += __shfl_down_sync(0xffffffffu, e, o);
        if (tid == 0) d_errp[ka*BATCH + s] = e;
    }
}

// commit: redundant per-block alpha choice, scatter-update X + support
__global__ void k_commit(float* __restrict__ X) {
    __shared__ int sc;
    int s = blockIdx.x, tid = threadIdx.x;
    if (tid == 0) {
        float l2 = 0.f;
        for (int s2 = 0; s2 < BATCH; s2++) l2 += d_l2p[s2];
        int c = NAL - 1;
        for (int k = 0; k < NAL; k++) {
            float e = 0.f;
            for (int s2 = 0; s2 < BATCH; s2++) e += d_errp[k*BATCH + s2];
            if (e < l2) { c = k; break; }
        }
        sc = c;
    }
    int ns = d_nsup[s];
    if (tid < ns) {
        int p = d_supp[s*KSEL + tid];
        if (p >= 0) X[s*NPS + p] = 0.f;
    }
    __syncthreads();
    int c = sc;
    int pos = d_selp[(c*BATCH + s)*KSEL + tid];
    float val = d_selv[(c*BATCH + s)*KSEL + tid];
    if (pos >= 0) X[s*NPS + pos] = val;
    d_supp[s*KSEL + tid] = pos;
    if (tid == 0) d_nsup[s] = KSEL;
}

// ---------------- launch ----------------
extern "C" void kernel_launch(void* const* d_in, const int* in_sizes, int n_in,
                              void* d_out, int out_size) {
    const float* Y  = (const float*)d_in[0];
    const float* Wg = (const float*)d_in[1];
    float* X = (float*)d_out;

    k_init<<<2048, 256>>>(X);
    for (int it = 0; it < 3; it++) {
        k_iter_init<<<512, 256>>>();
        k_residual<<<BATCH, 256>>>(Y, Wg, X);
        k_conv_g<<<1024, 256>>>(Wg);          // 4th launch on iter 0 -> profiled
        k_collect<<<dim3(52, BATCH), 256>>>(X);
        k_attempt<<<dim3(NAL, BATCH), 512>>>(Y, Wg);
        k_commit<<<BATCH, KSEL>>>(X);
    }
}

// round 7
// speedup vs baseline: 1.3225x; 1.0077x over previous
#include <cuda_runtime.h>

typedef unsigned long long ull;

#define BATCH 32
#define NATOM 128
#define HH 64
#define WW 64
#define OH 57
#define SPP (OH*OH)           // 3249
#define NPS (NATOM*SPP)       // 415872
#define KSEL 256
#define NAL 17
#define CAP 2048
#define NBINS 4096
#define IMGPIX (HH*WW)        // 4096

// ---------------- device state ----------------
__device__ float d_R[BATCH*IMGPIX];
__device__ float d_g[BATCH*NPS];              // ~53 MB (L2-resident)
__device__ int   d_hist[BATCH*NBINS];
__device__ int   d_ccnt[BATCH];
__device__ int   d_cpos[BATCH*CAP];
__device__ float d_cg[BATCH*CAP];
__device__ float d_cx[BATCH*CAP];
__device__ int   d_selp[NAL*BATCH*KSEL];
__device__ float d_selv[NAL*BATCH*KSEL];
__device__ float d_errp[NAL*BATCH];
__device__ float d_l2p[BATCH];
__device__ int   d_supp[BATCH*KSEL];
__device__ int   d_nsup[BATCH];

__device__ __forceinline__ int binof(float g) {
    return (int)((__float_as_uint(g) & 0x7fffffffu) >> 19);
}

// inclusive suffix sum over blockDim.x per-thread values
__device__ __forceinline__ int suffix_scan(int v, volatile int* wtmp, int nwarp) {
    int lane = threadIdx.x & 31, wid = threadIdx.x >> 5;
    int x = v;
    #pragma unroll
    for (int off = 1; off < 32; off <<= 1) {
        int u = __shfl_down_sync(0xffffffffu, x, off);
        if (lane + off < 32) x += u;
    }
    if (lane == 0) wtmp[wid] = x;
    __syncthreads();
    int add = 0;
    for (int j = wid + 1; j < nwarp; j++) add += wtmp[j];
    return x + add;
}

// ---------------- kernels ----------------

__global__ void k_init(float* __restrict__ X) {
    int stride = gridDim.x * blockDim.x;
    for (int i = blockIdx.x * blockDim.x + threadIdx.x; i < BATCH*NPS; i += stride)
        X[i] = 0.f;
    if (blockIdx.x == 0 && threadIdx.x < BATCH) d_nsup[threadIdx.x] = 0;
}

// residual R = Y - conv_D(X_sparse); per-sample l2; zero hist/ccnt
__global__ void k_residual(const float* __restrict__ Y, const float* __restrict__ Wg,
                           const float* __restrict__ X) {
    __shared__ float syh[IMGPIX];
    __shared__ float sred[8];
    int s = blockIdx.x, tid = threadIdx.x;
    if (tid == 0) d_ccnt[s] = 0;
    for (int i = tid; i < NBINS; i += 256) d_hist[s*NBINS + i] = 0;
    for (int i = tid; i < IMGPIX; i += 256) syh[i] = 0.f;
    __syncthreads();
    int ns = d_nsup[s];
    if (tid < ns) {
        int pos = d_supp[s*KSEL + tid];
        if (pos >= 0) {
            float val = X[s*NPS + pos];
            int a = pos / SPP, rem = pos - a*SPP, u = rem / OH, v = rem - u*OH;
            const float* w = Wg + a*64;
            #pragma unroll
            for (int p = 0; p < 8; p++)
                #pragma unroll
                for (int q = 0; q < 8; q++)
                    atomicAdd(&syh[(u+p)*WW + v + q], val * w[p*8 + q]);
        }
    }
    __syncthreads();
    float e = 0.f;
    for (int i = tid; i < IMGPIX; i += 256) {
        float r = Y[s*IMGPIX + i] - syh[i];
        d_R[s*IMGPIX + i] = r;
        e += r*r;
    }
    for (int o = 16; o; o >>= 1) e += __shfl_down_sync(0xffffffffu, e, o);
    if ((tid & 31) == 0) sred[tid >> 5] = e;
    __syncthreads();
    if (tid < 32) {
        e = (tid < 8) ? sred[tid] : 0.f;
        for (int o = 4; o; o >>= 1) e += __shfl_down_sync(0xffffffffu, e, o);
        if (tid == 0) d_l2p[s] = e;
    }
}

// g[b,a,u,v] = sum_{p,q} R[b,u+p,v+q] * W[a,q,p]; fused |g| histogram.
// Tile: 8 atoms x 32 u-rows per block (A=8, U=8 per thread -> LDS:FMA balanced).
// grid: 32 samples x 16 atom-groups x 2 u-chunks = 1024 blocks, 256 threads.
__global__ void __launch_bounds__(256) k_conv_g(const float* __restrict__ Wg) {
    __shared__ float shR[39*64 + 16];
    __shared__ float shW[64*8];       // [p*8+q][a]  (8 atoms)
    __shared__ int   shH[NBINS];
    int bid = blockIdx.x;
    int s   = bid >> 5;
    int rem = bid & 31;
    int grp = rem >> 1;       // 0..15 -> 8 atoms
    int uc  = rem & 1;        // 0..1  -> 32 u rows
    int ub  = uc * 32;
    int abase = grp * 8;
    int tid = threadIdx.x;

    for (int i = tid; i < NBINS; i += 256) shH[i] = 0;
    for (int i = tid; i < 39*64; i += 256) {
        int r = ub + (i >> 6);
        shR[i] = (r < HH) ? d_R[s*IMGPIX + r*WW + (i & 63)] : 0.f;
    }
    if (tid < 16) shR[39*64 + tid] = 0.f;
    for (int i = tid; i < 512; i += 256) {
        int a = i & 7, pq = i >> 3, p = pq >> 3, q = pq & 7;
        shW[pq*8 + a] = Wg[(abase + a)*64 + q*8 + p];
    }
    __syncthreads();

    int v  = tid & 63;
    int ty = tid >> 6;        // 0..3
    int u0 = ty * 8;          // local row base within 39-row window

    ull acc[4][8];
    #pragma unroll
    for (int ap = 0; ap < 4; ap++)
        #pragma unroll
        for (int uu = 0; uu < 8; uu++) acc[ap][uu] = 0ull;

    #pragma unroll 1
    for (int p = 0; p < 8; p++) {
        #pragma unroll
        for (int q = 0; q < 8; q++) {
            ull w2[4];
            const ull* wrow = (const ull*)&shW[(p*8 + q)*8];
            #pragma unroll
            for (int ap = 0; ap < 4; ap++) w2[ap] = wrow[ap];
            #pragma unroll
            for (int uu = 0; uu < 8; uu++) {
                float r = shR[(u0 + uu + p)*64 + v + q];
                ull r2;
                asm("mov.b64 %0, {%1, %1};" : "=l"(r2) : "f"(r));
                #pragma unroll
                for (int ap = 0; ap < 4; ap++)
                    asm("fma.rn.f32x2 %0, %1, %2, %0;"
                        : "+l"(acc[ap][uu]) : "l"(w2[ap]), "l"(r2));
            }
        }
    }

    bool vok = (v < OH);
    #pragma unroll
    for (int uu = 0; uu < 8; uu++) {
        int u = ub + u0 + uu;
        if (vok && u < OH) {
            int base = s*NPS + abase*SPP + u*OH + v;
            #pragma unroll
            for (int ap = 0; ap < 4; ap++) {
                float lo, hi;
                asm("mov.b64 {%0, %1}, %2;" : "=f"(lo), "=f"(hi) : "l"(acc[ap][uu]));
                d_g[base + (2*ap)*SPP]   = lo;
                d_g[base + (2*ap+1)*SPP] = hi;
                atomicAdd(&shH[binof(lo)], 1);
                atomicAdd(&shH[binof(hi)], 1);
            }
        }
    }
    __syncthreads();
    for (int i = tid; i < NBINS; i += 256)
        if (shH[i]) atomicAdd(&d_hist[s*NBINS + i], shH[i]);
}

// grid (52, 32): per-block redundant threshold (suffix scan over exact hist),
// chunks 0..50 scan dense g; chunk 51 appends support entries below threshold.
__global__ void __launch_bounds__(256) k_collect(const float* __restrict__ X) {
    __shared__ int wtmp[8];
    __shared__ int s_thr;
    int s = blockIdx.y, chunk = blockIdx.x, tid = threadIdx.x;

    const int* hist = &d_hist[s*NBINS];
    int seg = 0;
    #pragma unroll
    for (int j = 0; j < 16; j++) seg += hist[tid*16 + j];
    int ss = suffix_scan(seg, wtmp, 8);
    int low = ss - seg;
    if (ss >= 2*KSEL && low < 2*KSEL) {
        int cum = low;
        for (int j = 15; j >= 0; j--) {
            cum += hist[tid*16 + j];
            if (cum >= 2*KSEL) { s_thr = tid*16 + j; break; }
        }
    }
    __syncthreads();
    int thr = s_thr;

    if (chunk == 51) {
        int ns = d_nsup[s];
        if (tid < ns) {
            int pos = d_supp[s*KSEL + tid];
            if (pos >= 0) {
                float gv = d_g[s*NPS + pos];
                if (binof(gv) < thr) {
                    int idx = atomicAdd(&d_ccnt[s], 1);
                    if (idx < CAP) {
                        d_cpos[s*CAP + idx] = pos;
                        d_cg[s*CAP + idx]   = gv;
                        d_cx[s*CAP + idx]   = X[s*NPS + pos];
                    }
                }
            }
        }
        return;
    }
    int base = chunk * 8192;
    int end = base + 8192; if (end > NPS) end = NPS;
    for (int i = base + tid; i < end; i += 256) {
        float gv = d_g[s*NPS + i];
        if (binof(gv) >= thr) {
            int idx = atomicAdd(&d_ccnt[s], 1);
            if (idx < CAP) {
                d_cpos[s*CAP + idx] = i;
                d_cg[s*CAP + idx]   = gv;
                d_cx[s*CAP + idx]   = X[s*NPS + i];
            }
        }
    }
}

// one block per (alpha, sample): exact top-256 via 12-bit radix-select on unique
// 51-bit keys (abs<<19 | ~pos); then sparse reconstruction + err.
__global__ void __launch_bounds__(512) k_attempt(const float* __restrict__ Y,
                                                 const float* __restrict__ Wg) {
    __shared__ ull   skey[CAP];
    __shared__ float sval[CAP];
    __shared__ unsigned aux[NBINS];   // digit hist, later syh
    __shared__ int   wtmp[16];
    __shared__ ull   s_prefix, s_T;
    __shared__ int   s_m, s_done, s_cnt;
    __shared__ float sred[16];

    int ka = blockIdx.x, s = blockIdx.y, tid = threadIdx.x;
    float alpha = 1.0f / (float)(1 << ka);
    int n = d_ccnt[s]; if (n > CAP) n = CAP;

    for (int i = tid; i < CAP; i += 512) {
        ull kk = 0ull; float val = 0.f;
        if (i < n) {
            int pos = d_cpos[s*CAP + i];
            val = d_cx[s*CAP + i] + alpha * d_cg[s*CAP + i];
            unsigned ab = __float_as_uint(val) & 0x7fffffffu;
            kk = ((ull)ab << 19) | (unsigned)((~pos) & 0x7ffff);
        }
        skey[i] = kk; sval[i] = val;
    }
    if (tid == 0) { s_prefix = 0ull; s_m = KSEL; s_done = (n <= KSEL) ? 1 : 0; s_T = 1ull; }

    for (int lvl = 0; lvl < 5; lvl++) {
        __syncthreads();
        int done = s_done; ull pref = s_prefix; int m = s_m;
        int shift = 48 - 12*lvl;
        if (!done) {
            for (int i = tid; i < NBINS; i += 512) aux[i] = 0u;
            __syncthreads();
            ull himask = ~(((ull)1 << (shift + 12)) - 1);
            for (int i = tid; i < n; i += 512) {
                ull k = skey[i];
                if ((k & himask) == pref)
                    atomicAdd(&aux[(unsigned)((k >> shift) & 0xFFF)], 1u);
            }
            __syncthreads();
            int seg = 0;
            #pragma unroll
            for (int j = 0; j < 8; j++) seg += (int)aux[tid*8 + j];
            int ss = suffix_scan(seg, wtmp, 16);
            int low = ss - seg;
            if (ss >= m && low < m) {
                int cum = low, b = tid*8, h_b = 0;
                for (int j = 7; j >= 0; j--) {
                    int c = (int)aux[tid*8 + j];
                    cum += c;
                    if (cum >= m) { b = tid*8 + j; h_b = c; break; }
                }
                ull npref = pref | ((ull)b << shift);
                if (cum == m || shift == 0) { s_T = npref; s_done = 1; }
                else { s_prefix = npref; s_m = m - (cum - h_b); }
            }
        } else {
            __syncthreads();
        }
    }
    __syncthreads();
    ull T = s_T;

    int selbase = (ka*BATCH + s)*KSEL;
    if (tid < KSEL) d_selp[selbase + tid] = -1;
    for (int i = tid; i < IMGPIX; i += 512) aux[i] = 0u;
    if (tid == 0) s_cnt = 0;
    __syncthreads();

    float* syh = (float*)aux;
    for (int i = tid; i < n; i += 512) {
        ull k = skey[i];
        if (k >= T) {
            int slot = atomicAdd(&s_cnt, 1);
            int pos = (int)((~(unsigned)k) & 0x7ffff);
            float val = sval[i];
            d_selp[selbase + slot] = pos;
            d_selv[selbase + slot] = val;
            int a = pos / SPP, rem2 = pos - a*SPP, u = rem2 / OH, vv = rem2 - u*OH;
            const float* w = Wg + a*64;
            #pragma unroll
            for (int p = 0; p < 8; p++)
                #pragma unroll
                for (int q = 0; q < 8; q++)
                    atomicAdd(&syh[(u+p)*WW + vv + q], val * w[p*8 + q]);
        }
    }
    __syncthreads();
    float e = 0.f;
    for (int i = tid; i < IMGPIX; i += 512) {
        float d = Y[s*IMGPIX + i] - syh[i];
        e += d*d;
    }
    for (int o = 16; o; o >>= 1) e += __shfl_down_sync(0xffffffffu, e, o);
    if ((tid & 31) == 0) sred[tid >> 5] = e;
    __syncthreads();
    if (tid < 32) {
        e = (tid < 16) ? sred[tid] : 0.f;
        for (int o = 8; o; o >>= 1) e += __shfl_down_sync(0xffffffffu, e, o);
        if (tid == 0) d_errp[ka*BATCH + s] = e;
    }
}

// commit: parallel redundant alpha choice, scatter-update X + support
__global__ void k_commit(float* __restrict__ X) {
    __shared__ float serr[NAL];
    __shared__ float sl2;
    __shared__ int sc;
    int s = blockIdx.x, tid = threadIdx.x;
    if (tid < NAL) {
        float e = 0.f;
        for (int s2 = 0; s2 < BATCH; s2++) e += d_errp[tid*BATCH + s2];
        serr[tid] = e;
    }
    if (tid == 32) {
        float l2 = 0.f;
        for (int s2 = 0; s2 < BATCH; s2++) l2 += d_l2p[s2];
        sl2 = l2;
    }
    __syncthreads();
    if (tid == 0) {
        int c = NAL - 1;
        for (int k = 0; k < NAL; k++)
            if (serr[k] < sl2) { c = k; break; }
        sc = c;
    }
    int ns = d_nsup[s];
    if (tid < ns) {
        int p = d_supp[s*KSEL + tid];
        if (p >= 0) X[s*NPS + p] = 0.f;
    }
    __syncthreads();
    int c = sc;
    int pos = d_selp[(c*BATCH + s)*KSEL + tid];
    float val = d_selv[(c*BATCH + s)*KSEL + tid];
    if (pos >= 0) X[s*NPS + pos] = val;
    d_supp[s*KSEL + tid] = pos;
    if (tid == 0) d_nsup[s] = KSEL;
}

// ---------------- launch ----------------
extern "C" void kernel_launch(void* const* d_in, const int* in_sizes, int n_in,
                              void* d_out, int out_size) {
    const float* Y  = (const float*)d_in[0];
    const float* Wg = (const float*)d_in[1];
    float* X = (float*)d_out;

    k_init<<<2048, 256>>>(X);
    for (int it = 0; it < 3; it++) {
        k_residual<<<BATCH, 256>>>(Y, Wg, X);
        k_conv_g<<<1024, 256>>>(Wg);
        k_collect<<<dim3(52, BATCH), 256>>>(X);   // 4th launch -> profiled
        k_attempt<<<dim3(NAL, BATCH), 512>>>(Y, Wg);
        k_commit<<<BATCH, KSEL>>>(X);
    }
}

// round 8
// speedup vs baseline: 1.3898x; 1.0509x over previous
#include <cuda_runtime.h>

typedef unsigned long long ull;

#define BATCH 32
#define NATOM 128
#define HH 64
#define WW 64
#define OH 57
#define SPP (OH*OH)           // 3249
#define NPS (NATOM*SPP)       // 415872
#define KSEL 256
#define NAL 17
#define CAP 2048
#define NBINS 4096
#define IMGPIX (HH*WW)        // 4096
#define NVEC (NPS/4)          // 103968 float4s
#define VCHUNK 2048           // float4s per collect chunk (51 chunks)

// ---------------- device state ----------------
__device__ float d_R[BATCH*IMGPIX];
__device__ float d_g[BATCH*NPS];              // ~53 MB
__device__ int   d_hist[BATCH*NBINS];
__device__ int   d_ccnt[BATCH];
__device__ int   d_cpos[BATCH*CAP];
__device__ float d_cg[BATCH*CAP];
__device__ float d_cx[BATCH*CAP];
__device__ int   d_selp[NAL*BATCH*KSEL];
__device__ float d_selv[NAL*BATCH*KSEL];
__device__ float d_errp[NAL*BATCH];
__device__ float d_l2p[BATCH];
__device__ int   d_supp[BATCH*KSEL];
__device__ int   d_nsup[BATCH];

__device__ __forceinline__ int binof(float g) {
    return (int)((__float_as_uint(g) & 0x7fffffffu) >> 19);
}

// inclusive suffix sum over blockDim.x per-thread values
__device__ __forceinline__ int suffix_scan(int v, volatile int* wtmp, int nwarp) {
    int lane = threadIdx.x & 31, wid = threadIdx.x >> 5;
    int x = v;
    #pragma unroll
    for (int off = 1; off < 32; off <<= 1) {
        int u = __shfl_down_sync(0xffffffffu, x, off);
        if (lane + off < 32) x += u;
    }
    if (lane == 0) wtmp[wid] = x;
    __syncthreads();
    int add = 0;
    for (int j = wid + 1; j < nwarp; j++) add += wtmp[j];
    return x + add;
}

// ---------------- kernels ----------------

__global__ void k_init(float* __restrict__ X) {
    int stride = gridDim.x * blockDim.x;
    for (int i = blockIdx.x * blockDim.x + threadIdx.x; i < BATCH*NPS; i += stride)
        X[i] = 0.f;
    if (blockIdx.x == 0 && threadIdx.x < BATCH) d_nsup[threadIdx.x] = 0;
}

// residual R = Y - conv_D(X_sparse); per-sample l2; zero hist/ccnt
__global__ void k_residual(const float* __restrict__ Y, const float* __restrict__ Wg,
                           const float* __restrict__ X) {
    __shared__ float syh[IMGPIX];
    __shared__ float sred[8];
    int s = blockIdx.x, tid = threadIdx.x;
    if (tid == 0) d_ccnt[s] = 0;
    int4* h4 = (int4*)&d_hist[s*NBINS];
    int4 z4 = make_int4(0,0,0,0);
    for (int i = tid; i < NBINS/4; i += 256) h4[i] = z4;
    for (int i = tid; i < IMGPIX; i += 256) syh[i] = 0.f;
    __syncthreads();
    int ns = d_nsup[s];
    if (tid < ns) {
        int pos = d_supp[s*KSEL + tid];
        if (pos >= 0) {
            float val = X[s*NPS + pos];
            int a = pos / SPP, rem = pos - a*SPP, u = rem / OH, v = rem - u*OH;
            const float* w = Wg + a*64;
            #pragma unroll
            for (int p = 0; p < 8; p++)
                #pragma unroll
                for (int q = 0; q < 8; q++)
                    atomicAdd(&syh[(u+p)*WW + v + q], val * w[p*8 + q]);
        }
    }
    __syncthreads();
    float e = 0.f;
    for (int i = tid; i < IMGPIX; i += 256) {
        float r = Y[s*IMGPIX + i] - syh[i];
        d_R[s*IMGPIX + i] = r;
        e += r*r;
    }
    for (int o = 16; o; o >>= 1) e += __shfl_down_sync(0xffffffffu, e, o);
    if ((tid & 31) == 0) sred[tid >> 5] = e;
    __syncthreads();
    if (tid < 32) {
        e = (tid < 8) ? sred[tid] : 0.f;
        for (int o = 4; o; o >>= 1) e += __shfl_down_sync(0xffffffffu, e, o);
        if (tid == 0) d_l2p[s] = e;
    }
}

// g[b,a,u,v] = sum_{p,q} R[b,u+p,v+q] * W[a,q,p]; fused |g| histogram.
// Tile: 8 atoms x 32 u-rows per block (A=8, U=8 per thread -> LDS:FMA balanced).
__global__ void __launch_bounds__(256) k_conv_g(const float* __restrict__ Wg) {
    __shared__ float shR[39*64 + 16];
    __shared__ float shW[64*8];       // [p*8+q][a]
    __shared__ int   shH[NBINS];
    int bid = blockIdx.x;
    int s   = bid >> 5;
    int rem = bid & 31;
    int grp = rem >> 1;
    int uc  = rem & 1;
    int ub  = uc * 32;
    int abase = grp * 8;
    int tid = threadIdx.x;

    for (int i = tid; i < NBINS; i += 256) shH[i] = 0;
    for (int i = tid; i < 39*64; i += 256) {
        int r = ub + (i >> 6);
        shR[i] = (r < HH) ? d_R[s*IMGPIX + r*WW + (i & 63)] : 0.f;
    }
    if (tid < 16) shR[39*64 + tid] = 0.f;
    for (int i = tid; i < 512; i += 256) {
        int a = i & 7, pq = i >> 3, p = pq >> 3, q = pq & 7;
        shW[pq*8 + a] = Wg[(abase + a)*64 + q*8 + p];
    }
    __syncthreads();

    int v  = tid & 63;
    int ty = tid >> 6;
    int u0 = ty * 8;

    ull acc[4][8];
    #pragma unroll
    for (int ap = 0; ap < 4; ap++)
        #pragma unroll
        for (int uu = 0; uu < 8; uu++) acc[ap][uu] = 0ull;

    #pragma unroll 1
    for (int p = 0; p < 8; p++) {
        #pragma unroll
        for (int q = 0; q < 8; q++) {
            ull w2[4];
            const ull* wrow = (const ull*)&shW[(p*8 + q)*8];
            #pragma unroll
            for (int ap = 0; ap < 4; ap++) w2[ap] = wrow[ap];
            #pragma unroll
            for (int uu = 0; uu < 8; uu++) {
                float r = shR[(u0 + uu + p)*64 + v + q];
                ull r2;
                asm("mov.b64 %0, {%1, %1};" : "=l"(r2) : "f"(r));
                #pragma unroll
                for (int ap = 0; ap < 4; ap++)
                    asm("fma.rn.f32x2 %0, %1, %2, %0;"
                        : "+l"(acc[ap][uu]) : "l"(w2[ap]), "l"(r2));
            }
        }
    }

    bool vok = (v < OH);
    #pragma unroll
    for (int uu = 0; uu < 8; uu++) {
        int u = ub + u0 + uu;
        if (vok && u < OH) {
            int base = s*NPS + abase*SPP + u*OH + v;
            #pragma unroll
            for (int ap = 0; ap < 4; ap++) {
                float lo, hi;
                asm("mov.b64 {%0, %1}, %2;" : "=f"(lo), "=f"(hi) : "l"(acc[ap][uu]));
                d_g[base + (2*ap)*SPP]   = lo;
                d_g[base + (2*ap+1)*SPP] = hi;
                atomicAdd(&shH[binof(lo)], 1);
                atomicAdd(&shH[binof(hi)], 1);
            }
        }
    }
    __syncthreads();
    for (int i = tid; i < NBINS; i += 256)
        if (shH[i]) atomicAdd(&d_hist[s*NBINS + i], shH[i]);
}

// grid (52, 32): per-block redundant threshold, float4 scan of dense g.
// chunk 51 appends support entries below threshold.
__global__ void __launch_bounds__(256) k_collect(const float* __restrict__ X) {
    __shared__ int wtmp[8];
    __shared__ int s_thr;
    int s = blockIdx.y, chunk = blockIdx.x, tid = threadIdx.x;

    const int* hist = &d_hist[s*NBINS];
    int seg = 0;
    #pragma unroll
    for (int j = 0; j < 16; j++) seg += hist[tid*16 + j];
    int ss = suffix_scan(seg, wtmp, 8);
    int low = ss - seg;
    if (ss >= 2*KSEL && low < 2*KSEL) {
        int cum = low;
        for (int j = 15; j >= 0; j--) {
            cum += hist[tid*16 + j];
            if (cum >= 2*KSEL) { s_thr = tid*16 + j; break; }
        }
    }
    __syncthreads();
    int thr = s_thr;
    unsigned thrbits = (unsigned)thr << 19;   // binof(g) >= thr  <=>  abs-bits >= thrbits

    if (chunk == 51) {
        int ns = d_nsup[s];
        if (tid < ns) {
            int pos = d_supp[s*KSEL + tid];
            if (pos >= 0) {
                float gv = d_g[s*NPS + pos];
                if ((__float_as_uint(gv) & 0x7fffffffu) < thrbits) {
                    int idx = atomicAdd(&d_ccnt[s], 1);
                    if (idx < CAP) {
                        d_cpos[s*CAP + idx] = pos;
                        d_cg[s*CAP + idx]   = gv;
                        d_cx[s*CAP + idx]   = X[s*NPS + pos];
                    }
                }
            }
        }
        return;
    }

    const float4* g4 = (const float4*)&d_g[s*NPS];
    int base = chunk * VCHUNK;
    int end = base + VCHUNK; if (end > NVEC) end = NVEC;
    // 2-deep unrolled stream: 2 LDG.128 in flight per thread
    int i = base + tid;
    for (; i + 256 < end; i += 512) {
        float4 a = g4[i];
        float4 b = g4[i + 256];
        float va[8] = {a.x, a.y, a.z, a.w, b.x, b.y, b.z, b.w};
        #pragma unroll
        for (int l = 0; l < 8; l++) {
            if ((__float_as_uint(va[l]) & 0x7fffffffu) >= thrbits) {
                int pos = ((l < 4) ? i : (i + 256))*4 + (l & 3);
                int idx = atomicAdd(&d_ccnt[s], 1);
                if (idx < CAP) {
                    d_cpos[s*CAP + idx] = pos;
                    d_cg[s*CAP + idx]   = va[l];
                    d_cx[s*CAP + idx]   = X[s*NPS + pos];
                }
            }
        }
    }
    for (; i < end; i += 256) {
        float4 a = g4[i];
        float va[4] = {a.x, a.y, a.z, a.w};
        #pragma unroll
        for (int l = 0; l < 4; l++) {
            if ((__float_as_uint(va[l]) & 0x7fffffffu) >= thrbits) {
                int pos = i*4 + l;
                int idx = atomicAdd(&d_ccnt[s], 1);
                if (idx < CAP) {
                    d_cpos[s*CAP + idx] = pos;
                    d_cg[s*CAP + idx]   = va[l];
                    d_cx[s*CAP + idx]   = X[s*NPS + pos];
                }
            }
        }
    }
}

// one block per (alpha, sample): exact top-256 via 12-bit radix-select on unique
// 51-bit keys (abs<<19 | ~pos); then sparse reconstruction + err.
__global__ void __launch_bounds__(512) k_attempt(const float* __restrict__ Y,
                                                 const float* __restrict__ Wg) {
    __shared__ ull   skey[CAP];
    __shared__ float sval[CAP];
    __shared__ unsigned aux[NBINS];   // digit hist, later syh
    __shared__ int   wtmp[16];
    __shared__ ull   s_prefix, s_T;
    __shared__ int   s_m, s_done, s_cnt;
    __shared__ float sred[16];

    int ka = blockIdx.x, s = blockIdx.y, tid = threadIdx.x;
    float alpha = 1.0f / (float)(1 << ka);
    int n = d_ccnt[s]; if (n > CAP) n = CAP;

    for (int i = tid; i < CAP; i += 512) {
        ull kk = 0ull; float val = 0.f;
        if (i < n) {
            int pos = d_cpos[s*CAP + i];
            val = d_cx[s*CAP + i] + alpha * d_cg[s*CAP + i];
            unsigned ab = __float_as_uint(val) & 0x7fffffffu;
            kk = ((ull)ab << 19) | (unsigned)((~pos) & 0x7ffff);
        }
        skey[i] = kk; sval[i] = val;
    }
    if (tid == 0) { s_prefix = 0ull; s_m = KSEL; s_done = (n <= KSEL) ? 1 : 0; s_T = 1ull; }

    for (int lvl = 0; lvl < 5; lvl++) {
        __syncthreads();
        int done = s_done; ull pref = s_prefix; int m = s_m;
        int shift = 48 - 12*lvl;
        if (!done) {
            for (int i = tid; i < NBINS; i += 512) aux[i] = 0u;
            __syncthreads();
            ull himask = ~(((ull)1 << (shift + 12)) - 1);
            for (int i = tid; i < n; i += 512) {
                ull k = skey[i];
                if ((k & himask) == pref)
                    atomicAdd(&aux[(unsigned)((k >> shift) & 0xFFF)], 1u);
            }
            __syncthreads();
            int seg = 0;
            #pragma unroll
            for (int j = 0; j < 8; j++) seg += (int)aux[tid*8 + j];
            int ss = suffix_scan(seg, wtmp, 16);
            int low = ss - seg;
            if (ss >= m && low < m) {
                int cum = low, b = tid*8, h_b = 0;
                for (int j = 7; j >= 0; j--) {
                    int c = (int)aux[tid*8 + j];
                    cum += c;
                    if (cum >= m) { b = tid*8 + j; h_b = c; break; }
                }
                ull npref = pref | ((ull)b << shift);
                if (cum == m || shift == 0) { s_T = npref; s_done = 1; }
                else { s_prefix = npref; s_m = m - (cum - h_b); }
            }
        } else {
            __syncthreads();
        }
    }
    __syncthreads();
    ull T = s_T;

    int selbase = (ka*BATCH + s)*KSEL;
    if (tid < KSEL) d_selp[selbase + tid] = -1;
    for (int i = tid; i < IMGPIX; i += 512) aux[i] = 0u;
    if (tid == 0) s_cnt = 0;
    __syncthreads();

    float* syh = (float*)aux;
    for (int i = tid; i < n; i += 512) {
        ull k = skey[i];
        if (k >= T) {
            int slot = atomicAdd(&s_cnt, 1);
            int pos = (int)((~(unsigned)k) & 0x7ffff);
            float val = sval[i];
            d_selp[selbase + slot] = pos;
            d_selv[selbase + slot] = val;
            int a = pos / SPP, rem2 = pos - a*SPP, u = rem2 / OH, vv = rem2 - u*OH;
            const float* w = Wg + a*64;
            #pragma unroll
            for (int p = 0; p < 8; p++)
                #pragma unroll
                for (int q = 0; q < 8; q++)
                    atomicAdd(&syh[(u+p)*WW + vv + q], val * w[p*8 + q]);
        }
    }
    __syncthreads();
    float e = 0.f;
    for (int i = tid; i < IMGPIX; i += 512) {
        float d = Y[s*IMGPIX + i] - syh[i];
        e += d*d;
    }
    for (int o = 16; o; o >>= 1) e += __shfl_down_sync(0xffffffffu, e, o);
    if ((tid & 31) == 0) sred[tid >> 5] = e;
    __syncthreads();
    if (tid < 32) {
        e = (tid < 16) ? sred[tid] : 0.f;
        for (int o = 8; o; o >>= 1) e += __shfl_down_sync(0xffffffffu, e, o);
        if (tid == 0) d_errp[ka*BATCH + s] = e;
    }
}

// commit: parallel redundant alpha choice, scatter-update X + support
__global__ void k_commit(float* __restrict__ X) {
    __shared__ float serr[NAL];
    __shared__ float sl2;
    __shared__ int sc;
    int s = blockIdx.x, tid = threadIdx.x;
    if (tid < NAL) {
        float e = 0.f;
        for (int s2 = 0; s2 < BATCH; s2++) e += d_errp[tid*BATCH + s2];
        serr[tid] = e;
    }
    if (tid == 32) {
        float l2 = 0.f;
        for (int s2 = 0; s2 < BATCH; s2++) l2 += d_l2p[s2];
        sl2 = l2;
    }
    __syncthreads();
    if (tid == 0) {
        int c = NAL - 1;
        for (int k = 0; k < NAL; k++)
            if (serr[k] < sl2) { c = k; break; }
        sc = c;
    }
    int ns = d_nsup[s];
    if (tid < ns) {
        int p = d_supp[s*KSEL + tid];
        if (p >= 0) X[s*NPS + p] = 0.f;
    }
    __syncthreads();
    int c = sc;
    int pos = d_selp[(c*BATCH + s)*KSEL + tid];
    float val = d_selv[(c*BATCH + s)*KSEL + tid];
    if (pos >= 0) X[s*NPS + pos] = val;
    d_supp[s*KSEL + tid] = pos;
    if (tid == 0) d_nsup[s] = KSEL;
}

// ---------------- launch ----------------
extern "C" void kernel_launch(void* const* d_in, const int* in_sizes, int n_in,
                              void* d_out, int out_size) {
    const float* Y  = (const float*)d_in[0];
    const float* Wg = (const float*)d_in[1];
    float* X = (float*)d_out;

    k_init<<<2048, 256>>>(X);
    for (int it = 0; it < 3; it++) {
        k_residual<<<BATCH, 256>>>(Y, Wg, X);
        k_conv_g<<<1024, 256>>>(Wg);
        k_collect<<<dim3(52, BATCH), 256>>>(X);   // 4th launch -> profiled
        k_attempt<<<dim3(NAL, BATCH), 512>>>(Y, Wg);
        k_commit<<<BATCH, KSEL>>>(X);
    }
}

// round 9
// speedup vs baseline: 1.4150x; 1.0181x over previous
#include <cuda_runtime.h>

typedef unsigned long long ull;

#define BATCH 32
#define NATOM 128
#define HH 64
#define WW 64
#define OH 57
#define SPP (OH*OH)           // 3249
#define NPS (NATOM*SPP)       // 415872
#define KSEL 256
#define NAL 17
#define CAP 2048
#define NBINS 4096
#define IMGPIX (HH*WW)        // 4096
#define NVEC (NPS/4)          // 103968 float4s
#define VCHUNK 2048           // float4s per collect chunk (51 chunks)

// ---------------- device state ----------------
__device__ float d_R[BATCH*IMGPIX];
__device__ float d_g[BATCH*NPS];              // ~53 MB
__device__ int   d_hist[BATCH*NBINS];
__device__ int   d_ccnt[BATCH];
__device__ int   d_cpos[BATCH*CAP];
__device__ float d_cg[BATCH*CAP];
__device__ float d_cx[BATCH*CAP];
__device__ int   d_selp[NAL*BATCH*KSEL];
__device__ float d_selv[NAL*BATCH*KSEL];
__device__ float d_errp[NAL*BATCH];
__device__ float d_l2p[BATCH];
__device__ int   d_supp[BATCH*KSEL];
__device__ int   d_nsup[BATCH];

__device__ __forceinline__ int binof(float g) {
    return (int)((__float_as_uint(g) & 0x7fffffffu) >> 19);
}

// inclusive suffix sum over blockDim.x per-thread values
__device__ __forceinline__ int suffix_scan(int v, volatile int* wtmp, int nwarp) {
    int lane = threadIdx.x & 31, wid = threadIdx.x >> 5;
    int x = v;
    #pragma unroll
    for (int off = 1; off < 32; off <<= 1) {
        int u = __shfl_down_sync(0xffffffffu, x, off);
        if (lane + off < 32) x += u;
    }
    if (lane == 0) wtmp[wid] = x;
    __syncthreads();
    int add = 0;
    for (int j = wid + 1; j < nwarp; j++) add += wtmp[j];
    return x + add;
}

// ---------------- kernels ----------------

__global__ void k_init(float* __restrict__ X) {
    float4* X4 = (float4*)X;
    int stride = gridDim.x * blockDim.x;
    float4 z = make_float4(0.f, 0.f, 0.f, 0.f);
    for (int i = blockIdx.x * blockDim.x + threadIdx.x; i < BATCH*NPS/4; i += stride)
        X4[i] = z;
    if (blockIdx.x == 0 && threadIdx.x < BATCH) d_nsup[threadIdx.x] = 0;
}

// residual R = Y - conv_D(X_sparse); per-sample l2; zero hist/ccnt
__global__ void k_residual(const float* __restrict__ Y, const float* __restrict__ Wg,
                           const float* __restrict__ X) {
    __shared__ float syh[IMGPIX];
    __shared__ float sred[8];
    int s = blockIdx.x, tid = threadIdx.x;
    if (tid == 0) d_ccnt[s] = 0;
    int4* h4 = (int4*)&d_hist[s*NBINS];
    int4 z4 = make_int4(0,0,0,0);
    for (int i = tid; i < NBINS/4; i += 256) h4[i] = z4;
    for (int i = tid; i < IMGPIX; i += 256) syh[i] = 0.f;
    __syncthreads();
    int ns = d_nsup[s];
    if (tid < ns) {
        int pos = d_supp[s*KSEL + tid];
        if (pos >= 0) {
            float val = X[s*NPS + pos];
            int a = pos / SPP, rem = pos - a*SPP, u = rem / OH, v = rem - u*OH;
            const float* w = Wg + a*64;
            #pragma unroll
            for (int p = 0; p < 8; p++)
                #pragma unroll
                for (int q = 0; q < 8; q++)
                    atomicAdd(&syh[(u+p)*WW + v + q], val * w[p*8 + q]);
        }
    }
    __syncthreads();
    float e = 0.f;
    for (int i = tid; i < IMGPIX; i += 256) {
        float r = Y[s*IMGPIX + i] - syh[i];
        d_R[s*IMGPIX + i] = r;
        e += r*r;
    }
    for (int o = 16; o; o >>= 1) e += __shfl_down_sync(0xffffffffu, e, o);
    if ((tid & 31) == 0) sred[tid >> 5] = e;
    __syncthreads();
    if (tid < 32) {
        e = (tid < 8) ? sred[tid] : 0.f;
        for (int o = 4; o; o >>= 1) e += __shfl_down_sync(0xffffffffu, e, o);
        if (tid == 0) d_l2p[s] = e;
    }
}

// g[b,a,u,v] = sum_{p,q} R[b,u+p,v+q] * W[a,q,p]; fused |g| histogram.
// Tile: 8 atoms x 32 u-rows per block (A=8, U=8 per thread -> LDS:FMA balanced).
__global__ void __launch_bounds__(256) k_conv_g(const float* __restrict__ Wg) {
    __shared__ float shR[39*64 + 16];
    __shared__ float shW[64*8];       // [p*8+q][a]
    __shared__ int   shH[NBINS];
    int bid = blockIdx.x;
    int s   = bid >> 5;
    int rem = bid & 31;
    int grp = rem >> 1;
    int uc  = rem & 1;
    int ub  = uc * 32;
    int abase = grp * 8;
    int tid = threadIdx.x;

    for (int i = tid; i < NBINS; i += 256) shH[i] = 0;
    for (int i = tid; i < 39*64; i += 256) {
        int r = ub + (i >> 6);
        shR[i] = (r < HH) ? d_R[s*IMGPIX + r*WW + (i & 63)] : 0.f;
    }
    if (tid < 16) shR[39*64 + tid] = 0.f;
    for (int i = tid; i < 512; i += 256) {
        int a = i & 7, pq = i >> 3, p = pq >> 3, q = pq & 7;
        shW[pq*8 + a] = Wg[(abase + a)*64 + q*8 + p];
    }
    __syncthreads();

    int v  = tid & 63;
    int ty = tid >> 6;
    int u0 = ty * 8;

    ull acc[4][8];
    #pragma unroll
    for (int ap = 0; ap < 4; ap++)
        #pragma unroll
        for (int uu = 0; uu < 8; uu++) acc[ap][uu] = 0ull;

    #pragma unroll 1
    for (int p = 0; p < 8; p++) {
        #pragma unroll
        for (int q = 0; q < 8; q++) {
            ull w2[4];
            const ull* wrow = (const ull*)&shW[(p*8 + q)*8];
            #pragma unroll
            for (int ap = 0; ap < 4; ap++) w2[ap] = wrow[ap];
            #pragma unroll
            for (int uu = 0; uu < 8; uu++) {
                float r = shR[(u0 + uu + p)*64 + v + q];
                ull r2;
                asm("mov.b64 %0, {%1, %1};" : "=l"(r2) : "f"(r));
                #pragma unroll
                for (int ap = 0; ap < 4; ap++)
                    asm("fma.rn.f32x2 %0, %1, %2, %0;"
                        : "+l"(acc[ap][uu]) : "l"(w2[ap]), "l"(r2));
            }
        }
    }

    bool vok = (v < OH);
    #pragma unroll
    for (int uu = 0; uu < 8; uu++) {
        int u = ub + u0 + uu;
        if (vok && u < OH) {
            int base = s*NPS + abase*SPP + u*OH + v;
            #pragma unroll
            for (int ap = 0; ap < 4; ap++) {
                float lo, hi;
                asm("mov.b64 {%0, %1}, %2;" : "=f"(lo), "=f"(hi) : "l"(acc[ap][uu]));
                d_g[base + (2*ap)*SPP]   = lo;
                d_g[base + (2*ap+1)*SPP] = hi;
                atomicAdd(&shH[binof(lo)], 1);
                atomicAdd(&shH[binof(hi)], 1);
            }
        }
    }
    __syncthreads();
    for (int i = tid; i < NBINS; i += 256)
        if (shH[i]) atomicAdd(&d_hist[s*NBINS + i], shH[i]);
}

// grid (52, 32): per-block redundant threshold, 4-deep float4 scan of dense g.
// chunk 51 appends support entries below threshold.
__global__ void __launch_bounds__(256) k_collect(const float* __restrict__ X) {
    __shared__ int wtmp[8];
    __shared__ int s_thr;
    int s = blockIdx.y, chunk = blockIdx.x, tid = threadIdx.x;

    const int* hist = &d_hist[s*NBINS];
    int seg = 0;
    #pragma unroll
    for (int j = 0; j < 16; j++) seg += hist[tid*16 + j];
    int ss = suffix_scan(seg, wtmp, 8);
    int low = ss - seg;
    if (ss >= 2*KSEL && low < 2*KSEL) {
        int cum = low;
        for (int j = 15; j >= 0; j--) {
            cum += hist[tid*16 + j];
            if (cum >= 2*KSEL) { s_thr = tid*16 + j; break; }
        }
    }
    __syncthreads();
    int thr = s_thr;
    unsigned thrbits = (unsigned)thr << 19;   // binof(g) >= thr  <=>  abs-bits >= thrbits

    if (chunk == 51) {
        int ns = d_nsup[s];
        if (tid < ns) {
            int pos = d_supp[s*KSEL + tid];
            if (pos >= 0) {
                float gv = d_g[s*NPS + pos];
                if ((__float_as_uint(gv) & 0x7fffffffu) < thrbits) {
                    int idx = atomicAdd(&d_ccnt[s], 1);
                    if (idx < CAP) {
                        d_cpos[s*CAP + idx] = pos;
                        d_cg[s*CAP + idx]   = gv;
                        d_cx[s*CAP + idx]   = X[s*NPS + pos];
                    }
                }
            }
        }
        return;
    }

    const float4* g4 = (const float4*)&d_g[s*NPS];
    int base = chunk * VCHUNK;
    int end = base + VCHUNK; if (end > NVEC) end = NVEC;
    // 4-deep stream: 4 LDG.128 in flight per thread per step
    int i = base + tid;
    for (; i + 768 < end; i += 1024) {
        float4 a = g4[i];
        float4 b = g4[i + 256];
        float4 c = g4[i + 512];
        float4 d = g4[i + 768];
        float va[16] = {a.x,a.y,a.z,a.w, b.x,b.y,b.z,b.w,
                        c.x,c.y,c.z,c.w, d.x,d.y,d.z,d.w};
        #pragma unroll
        for (int l = 0; l < 16; l++) {
            if ((__float_as_uint(va[l]) & 0x7fffffffu) >= thrbits) {
                int pos = (i + (l >> 2)*256)*4 + (l & 3);
                int idx = atomicAdd(&d_ccnt[s], 1);
                if (idx < CAP) {
                    d_cpos[s*CAP + idx] = pos;
                    d_cg[s*CAP + idx]   = va[l];
                    d_cx[s*CAP + idx]   = X[s*NPS + pos];
                }
            }
        }
    }
    for (; i < end; i += 256) {
        float4 a = g4[i];
        float va[4] = {a.x, a.y, a.z, a.w};
        #pragma unroll
        for (int l = 0; l < 4; l++) {
            if ((__float_as_uint(va[l]) & 0x7fffffffu) >= thrbits) {
                int pos = i*4 + l;
                int idx = atomicAdd(&d_ccnt[s], 1);
                if (idx < CAP) {
                    d_cpos[s*CAP + idx] = pos;
                    d_cg[s*CAP + idx]   = va[l];
                    d_cx[s*CAP + idx]   = X[s*NPS + pos];
                }
            }
        }
    }
}

// one block per (alpha, sample): exact top-256 via 12-bit radix-select on unique
// 51-bit keys (abs<<19 | ~pos); then sparse reconstruction + err.
__global__ void __launch_bounds__(512) k_attempt(const float* __restrict__ Y,
                                                 const float* __restrict__ Wg) {
    __shared__ ull   skey[CAP];
    __shared__ float sval[CAP];
    __shared__ unsigned aux[NBINS];   // digit hist, later syh
    __shared__ int   wtmp[16];
    __shared__ ull   s_prefix, s_T;
    __shared__ int   s_m, s_done, s_cnt;
    __shared__ float sred[16];

    int ka = blockIdx.x, s = blockIdx.y, tid = threadIdx.x;
    float alpha = 1.0f / (float)(1 << ka);
    int n = d_ccnt[s]; if (n > CAP) n = CAP;

    for (int i = tid; i < n; i += 512) {
        int pos = d_cpos[s*CAP + i];
        float val = d_cx[s*CAP + i] + alpha * d_cg[s*CAP + i];
        unsigned ab = __float_as_uint(val) & 0x7fffffffu;
        skey[i] = ((ull)ab << 19) | (unsigned)((~pos) & 0x7ffff);
        sval[i] = val;
    }
    if (tid == 0) { s_prefix = 0ull; s_m = KSEL; s_done = (n <= KSEL) ? 1 : 0; s_T = 1ull; }

    for (int lvl = 0; lvl < 5; lvl++) {
        __syncthreads();
        int done = s_done; ull pref = s_prefix; int m = s_m;
        int shift = 48 - 12*lvl;
        if (!done) {
            for (int i = tid; i < NBINS; i += 512) aux[i] = 0u;
            __syncthreads();
            ull himask = ~(((ull)1 << (shift + 12)) - 1);
            for (int i = tid; i < n; i += 512) {
                ull k = skey[i];
                if ((k & himask) == pref)
                    atomicAdd(&aux[(unsigned)((k >> shift) & 0xFFF)], 1u);
            }
            __syncthreads();
            int seg = 0;
            #pragma unroll
            for (int j = 0; j < 8; j++) seg += (int)aux[tid*8 + j];
            int ss = suffix_scan(seg, wtmp, 16);
            int low = ss - seg;
            if (ss >= m && low < m) {
                int cum = low, b = tid*8, h_b = 0;
                for (int j = 7; j >= 0; j--) {
                    int c = (int)aux[tid*8 + j];
                    cum += c;
                    if (cum >= m) { b = tid*8 + j; h_b = c; break; }
                }
                ull npref = pref | ((ull)b << shift);
                if (cum == m || shift == 0) { s_T = npref; s_done = 1; }
                else { s_prefix = npref; s_m = m - (cum - h_b); }
            }
        } else {
            __syncthreads();
        }
    }
    __syncthreads();
    ull T = s_T;

    int selbase = (ka*BATCH + s)*KSEL;
    if (tid < KSEL) d_selp[selbase + tid] = -1;
    for (int i = tid; i < IMGPIX; i += 512) aux[i] = 0u;
    if (tid == 0) s_cnt = 0;
    __syncthreads();

    float* syh = (float*)aux;
    for (int i = tid; i < n; i += 512) {
        ull k = skey[i];
        if (k >= T) {
            int slot = atomicAdd(&s_cnt, 1);
            int pos = (int)((~(unsigned)k) & 0x7ffff);
            float val = sval[i];
            d_selp[selbase + slot] = pos;
            d_selv[selbase + slot] = val;
            int a = pos / SPP, rem2 = pos - a*SPP, u = rem2 / OH, vv = rem2 - u*OH;
            const float* w = Wg + a*64;
            #pragma unroll
            for (int p = 0; p < 8; p++)
                #pragma unroll
                for (int q = 0; q < 8; q++)
                    atomicAdd(&syh[(u+p)*WW + vv + q], val * w[p*8 + q]);
        }
    }
    __syncthreads();
    float e = 0.f;
    for (int i = tid; i < IMGPIX; i += 512) {
        float d = Y[s*IMGPIX + i] - syh[i];
        e += d*d;
    }
    for (int o = 16; o; o >>= 1) e += __shfl_down_sync(0xffffffffu, e, o);
    if ((tid & 31) == 0) sred[tid >> 5] = e;
    __syncthreads();
    if (tid < 32) {
        e = (tid < 16) ? sred[tid] : 0.f;
        for (int o = 8; o; o >>= 1) e += __shfl_down_sync(0xffffffffu, e, o);
        if (tid == 0) d_errp[ka*BATCH + s] = e;
    }
}

// commit: parallel redundant alpha choice, scatter-update X + support
__global__ void k_commit(float* __restrict__ X) {
    __shared__ float serr[NAL];
    __shared__ float sl2;
    __shared__ int sc;
    int s = blockIdx.x, tid = threadIdx.x;
    if (tid < NAL) {
        float e = 0.f;
        for (int s2 = 0; s2 < BATCH; s2++) e += d_errp[tid*BATCH + s2];
        serr[tid] = e;
    }
    if (tid == 32) {
        float l2 = 0.f;
        for (int s2 = 0; s2 < BATCH; s2++) l2 += d_l2p[s2];
        sl2 = l2;
    }
    __syncthreads();
    if (tid == 0) {
        int c = NAL - 1;
        for (int k = 0; k < NAL; k++)
            if (serr[k] < sl2) { c = k; break; }
        sc = c;
    }
    int ns = d_nsup[s];
    if (tid < ns) {
        int p = d_supp[s*KSEL + tid];
        if (p >= 0) X[s*NPS + p] = 0.f;
    }
    __syncthreads();
    int c = sc;
    int pos = d_selp[(c*BATCH + s)*KSEL + tid];
    float val = d_selv[(c*BATCH + s)*KSEL + tid];
    if (pos >= 0) X[s*NPS + pos] = val;
    d_supp[s*KSEL + tid] = pos;
    if (tid == 0) d_nsup[s] = KSEL;
}

// ---------------- launch ----------------
extern "C" void kernel_launch(void* const* d_in, const int* in_sizes, int n_in,
                              void* d_out, int out_size) {
    const float* Y  = (const float*)d_in[0];
    const float* Wg = (const float*)d_in[1];
    float* X = (float*)d_out;

    k_init<<<2048, 256>>>(X);
    for (int it = 0; it < 3; it++) {
        k_residual<<<BATCH, 256>>>(Y, Wg, X);
        k_conv_g<<<1024, 256>>>(Wg);
        k_collect<<<dim3(52, BATCH), 256>>>(X);   // 4th launch -> profiled
        k_attempt<<<dim3(NAL, BATCH), 512>>>(Y, Wg);
        k_commit<<<BATCH, KSEL>>>(X);
    }
}